// round 8
// baseline (speedup 1.0000x reference)
#include <cuda_runtime.h>

#define CLASS_NUM 80
#define K_DET 300
#define MAXC 256           // pool cap == nms parallel width; mean V~66
#define NW_MAX 8           // ceil(MAXC/32)
#define MAX_IMG 256
#define TPI 10647          // 3*(13^2+26^2+52^2)

// ---- global scratch, zero-initialized at module load ----
__device__ int   g_cnt [MAX_IMG];   // candidates per image
__device__ int   g_ctas[MAX_IMG];   // scan CTAs completed per image
__device__ float g_conf[MAX_IMG * MAXC];
__device__ float g_ox  [MAX_IMG * MAXC];
__device__ float g_oy  [MAX_IMG * MAXC];
__device__ float g_w   [MAX_IMG * MAXC];
__device__ float g_h   [MAX_IMG * MAXC];
__device__ int   g_cls [MAX_IMG * MAXC];
__device__ int   g_flat[MAX_IMG * MAXC];

__global__ __launch_bounds__(256) void fused_kernel(
    const float* __restrict__ o13, const float* __restrict__ o26, const float* __restrict__ o52,
    const float* __restrict__ a13, const float* __restrict__ a26, const float* __restrict__ a52,
    const float* __restrict__ pthresh, float* __restrict__ out, int total)
{
    const int tid  = threadIdx.x;
    const int lane = tid & 31;
    const int gid  = blockIdx.x * 256 + tid;

    // ---- NMS shared state (used only by finisher CTAs in the tail) ----
    __shared__ float c_conf[MAXC];
    __shared__ int   c_flat[MAXC];
    __shared__ float r_conf[MAXC], r_ox[MAXC], r_oy[MAXC], r_w[MAXC], r_h[MAXC];
    __shared__ float r_x1[MAXC], r_y1[MAXC], r_x2[MAXC], r_y2[MAXC];
    __shared__ int   r_cls[MAXC];
    __shared__ unsigned int supw[MAXC * NW_MAX];
    __shared__ unsigned char keepf[MAXC];
    __shared__ int s_do[2];

    if (tid < 2) s_do[tid] = -1;

    // ================= Phase A: scan + decode =================
    bool  hit = false;
    float conf = 0.f, ox = 0.f, oy = 0.f, w = 0.f, h = 0.f;
    int   n = 0, flat = 0, sHW = 0;
    const float* cp = nullptr;

    if (gid < total) {
        n = gid / TPI;
        const int idx = gid - n * TPI;
        const float thresh = __ldg(pthresh);

        if (idx < 507) {
            const int HW = 169, H = 13;
            const int a = idx / HW, cell = idx - a * HW;
            const float* base = o13 + (size_t)n * 255 * HW;
            conf = base[(a * 85) * HW + cell];
            if (conf > thresh) {
                hit = true; sHW = HW;
                const int y = cell / H, x = cell - y * H;
                const float t1 = base[(a * 85 + 1) * HW + cell];
                const float t2 = base[(a * 85 + 2) * HW + cell];
                const float t3 = base[(a * 85 + 3) * HW + cell];
                const float t4 = base[(a * 85 + 4) * HW + cell];
                ox = ((float)x + t1) * 32.f;
                oy = ((float)y + t2) * 32.f;
                w  = expf(t3) * a13[a * 2 + 0];
                h  = expf(t4) * a13[a * 2 + 1];
                cp = base + (a * 85 + 5) * HW + cell;
                flat = 0 + cell * 3 + a;
            }
        } else if (idx < 2535) {
            const int HW = 676, H = 26;
            const int p = idx - 507;
            const int a = p / HW, cell = p - a * HW;
            const float* base = o26 + (size_t)n * 255 * HW;
            conf = base[(a * 85) * HW + cell];
            if (conf > thresh) {
                hit = true; sHW = HW;
                const int y = cell / H, x = cell - y * H;
                const float t1 = base[(a * 85 + 1) * HW + cell];
                const float t2 = base[(a * 85 + 2) * HW + cell];
                const float t3 = base[(a * 85 + 3) * HW + cell];
                const float t4 = base[(a * 85 + 4) * HW + cell];
                ox = ((float)x + t1) * 16.f;
                oy = ((float)y + t2) * 16.f;
                w  = expf(t3) * a26[a * 2 + 0];
                h  = expf(t4) * a26[a * 2 + 1];
                cp = base + (a * 85 + 5) * HW + cell;
                flat = 507 + cell * 3 + a;
            }
        } else {
            const int HW = 2704, H = 52;
            const int p = idx - 2535;
            const int a = p / HW, cell = p - a * HW;
            const float* base = o52 + (size_t)n * 255 * HW;
            conf = base[(a * 85) * HW + cell];
            if (conf > thresh) {
                hit = true; sHW = HW;
                const int y = cell / H, x = cell - y * H;
                const float t1 = base[(a * 85 + 1) * HW + cell];
                const float t2 = base[(a * 85 + 2) * HW + cell];
                const float t3 = base[(a * 85 + 3) * HW + cell];
                const float t4 = base[(a * 85 + 4) * HW + cell];
                ox = ((float)x + t1) * 8.f;
                oy = ((float)y + t2) * 8.f;
                w  = expf(t3) * a52[a * 2 + 0];
                h  = expf(t4) * a52[a * 2 + 1];
                cp = base + (a * 85 + 5) * HW + cell;
                flat = 2535 + cell * 3 + a;
            }
        }
    }

    // warp-cooperative argmax over 80 classes per candidate
    unsigned int mask = __ballot_sync(0xffffffffu, hit);
    while (mask) {
        const int src = __ffs(mask) - 1;
        mask &= mask - 1;

        const float* scp = (const float*)__shfl_sync(0xffffffffu, (unsigned long long)cp, src);
        const int    sH  = __shfl_sync(0xffffffffu, sHW, src);

        float bv = scp[(size_t)lane * sH];
        int   bk = lane;
        {
            const float v = scp[(size_t)(lane + 32) * sH];
            if (v > bv) { bv = v; bk = lane + 32; }
        }
        if (lane < 16) {
            const float v = scp[(size_t)(lane + 64) * sH];
            if (v > bv) { bv = v; bk = lane + 64; }
        }
        #pragma unroll
        for (int off = 16; off > 0; off >>= 1) {
            const float ov = __shfl_xor_sync(0xffffffffu, bv, off);
            const int   ok = __shfl_xor_sync(0xffffffffu, bk, off);
            if (ov > bv || (ov == bv && ok < bk)) { bv = ov; bk = ok; }
        }

        if (lane == src) {
            const int pos = atomicAdd(&g_cnt[n], 1);
            if (pos < MAXC) {
                const int o = n * MAXC + pos;
                g_conf[o] = conf;
                g_ox[o]   = ox;  g_oy[o] = oy;
                g_w[o]    = w;   g_h[o]  = h;
                g_cls[o]  = bk;
                g_flat[o] = flat;
            }
        }
    }
    __syncthreads();   // all pool writes of this CTA issued

    // ================= Phase B: one atomic per touched image; elect finisher =================
    if (tid == 0) {
        const int g0 = blockIdx.x * 256;
        const int g1 = min(g0 + 255, total - 1);
        const int nf = g0 / TPI;
        const int nl = g1 / TPI;
        __threadfence();   // release: pool writes visible before the count
        for (int m = nf; m <= nl; m++) {
            const int sb   = (m * TPI) >> 8;              // first block of image m
            const int eb   = ((m + 1) * TPI - 1) >> 8;    // last block of image m
            const int need = eb - sb + 1;
            const int old  = atomicAdd(&g_ctas[m], 1);
            if (old + 1 == need) {
                __threadfence();                          // acquire side
                s_do[m - nf] = m;
            }
        }
    }
    __syncthreads();

    // ================= Phase C: finisher runs lean NMS for its image(s) =================
    for (int k = 0; k < 2; k++) {
        const int m = s_do[k];   // uniform across CTA
        if (m < 0) continue;

        // unconditional pool load (1 entry/thread), concurrent with count load
        const int o = m * MAXC + tid;
        const float cf = __ldcg(&g_conf[o]);
        const float px = __ldcg(&g_ox[o]), py = __ldcg(&g_oy[o]);
        const float pw = __ldcg(&g_w[o]),  ph = __ldcg(&g_h[o]);
        const int   pc = __ldcg(&g_cls[o]), pf = __ldcg(&g_flat[o]);
        const int   V  = min(__ldcg(&g_cnt[m]), MAXC);
        const int   K  = V;   // V <= MAXC=256 <= K_DET

        c_conf[tid] = cf;
        c_flat[tid] = pf;
        __syncthreads();

        // rank (conf desc, tie: flat asc)
        if (tid < V) {
            int r = 0;
            for (int j = 0; j < V; j++) {
                const float cj = c_conf[j];
                if (cj > cf || (cj == cf && c_flat[j] < pf)) r++;
            }
            r_conf[r] = cf;
            r_ox[r] = px; r_oy[r] = py;
            r_w[r]  = pw; r_h[r]  = ph;
            r_cls[r] = pc;
            const float hw = pw * 0.5f, hh = ph * 0.5f;
            r_x1[r] = px - hw; r_y1[r] = py - hh;
            r_x2[r] = px + hw; r_y2[r] = py + hh;
        }
        __syncthreads();

        // suppression bit-matrix
        const int NW = (K + 31) >> 5;
        for (int t = tid; t < K * NW; t += 256) {
            const int i  = t / NW;
            const int wj = t - i * NW;
            const float x1i = r_x1[i], y1i = r_y1[i], x2i = r_x2[i], y2i = r_y2[i];
            const float areai = (x2i - x1i) * (y2i - y1i);
            const int   ci = r_cls[i];
            unsigned int word = 0;
            const int jmax = min(K, (wj + 1) * 32);
            for (int j = wj * 32; j < jmax; j++) {
                if (r_cls[j] != ci) continue;
                const float ix1 = fmaxf(x1i, r_x1[j]);
                const float iy1 = fmaxf(y1i, r_y1[j]);
                const float ix2 = fminf(x2i, r_x2[j]);
                const float iy2 = fminf(y2i, r_y2[j]);
                const float iw = fmaxf(ix2 - ix1, 0.f);
                const float ih = fmaxf(iy2 - iy1, 0.f);
                const float inter = iw * ih;
                const float areaj = (r_x2[j] - r_x1[j]) * (r_y2[j] - r_y1[j]);
                const float uni   = fmaxf(areai + areaj - inter, 1e-9f);
                if (inter / uni > 0.3f) word |= (1u << (j & 31));
            }
            supw[i * NW + wj] = word;
        }
        __syncthreads();

        // sequential greedy scan + per-image scratch reset
        if (tid == 0) {
            unsigned int kw[NW_MAX];
            #pragma unroll
            for (int ww = 0; ww < NW_MAX; ww++) kw[ww] = 0u;
            for (int i = 0; i < K; i++) {
                unsigned int sup = 0;
                for (int ww = 0; ww < NW; ww++) sup |= kw[ww] & supw[i * NW + ww];
                if (sup == 0u) {
                    kw[i >> 5] |= (1u << (i & 31));
                    keepf[i] = 1;
                } else {
                    keepf[i] = 0;
                }
            }
            g_cnt[m]  = 0;
            g_ctas[m] = 0;
        }
        __syncthreads();

        // dense write: all 300x7 rows for this image (zeros where not kept)
        const float fm = (float)m;
        float* orow = out + (size_t)m * (K_DET * 7);
        for (int e = tid; e < K_DET * 7; e += 256) {
            const int i = e / 7;
            const int f = e - i * 7;
            float v = 0.f;
            if (i < K && keepf[i]) {
                switch (f) {
                    case 0: v = r_conf[i]; break;
                    case 1: v = r_ox[i];   break;
                    case 2: v = r_oy[i];   break;
                    case 3: v = r_w[i];    break;
                    case 4: v = r_h[i];    break;
                    case 5: v = (float)r_cls[i]; break;
                    case 6: v = fm;        break;
                }
            }
            orow[e] = v;
        }
        __syncthreads();
    }
}

extern "C" void kernel_launch(void* const* d_in, const int* in_sizes, int n_in,
                              void* d_out, int out_size) {
    const float* o13 = (const float*)d_in[0];
    const float* o26 = (const float*)d_in[1];
    const float* o52 = (const float*)d_in[2];
    const float* a13 = (const float*)d_in[3];
    const float* a26 = (const float*)d_in[4];
    const float* a52 = (const float*)d_in[5];
    const float* thr = (const float*)d_in[6];
    float* out = (float*)d_out;

    const int N = in_sizes[0] / (255 * 13 * 13);   // batch (=64)
    const int total = N * TPI;
    fused_kernel<<<(total + 255) / 256, 256>>>(o13, o26, o52, a13, a26, a52, thr, out, total);
}

// round 9
// speedup vs baseline: 1.5993x; 1.5993x over previous
#include <cuda_runtime.h>

#define CLASS_NUM 80
#define K_DET 300
#define MAXC 256           // == nms blockDim; mean V~66
#define NW_MAX 8           // ceil(MAXC/32)
#define MAX_IMG 256
#define TPI 10647          // 3*(13^2+26^2+52^2)

// ---- global scratch (per-image candidate pools), zero-initialized ----
__device__ int   g_cnt [MAX_IMG];
__device__ float g_conf[MAX_IMG * MAXC];
__device__ float g_ox  [MAX_IMG * MAXC];
__device__ float g_oy  [MAX_IMG * MAXC];
__device__ float g_w   [MAX_IMG * MAXC];
__device__ float g_h   [MAX_IMG * MAXC];
__device__ int   g_cls [MAX_IMG * MAXC];
__device__ int   g_flat[MAX_IMG * MAXC];

// ============ Kernel A: 4-cell-per-thread scan + decode + output zero-fill ============
__global__ __launch_bounds__(256) void scan_kernel(
    const float* __restrict__ o13, const float* __restrict__ o26, const float* __restrict__ o52,
    const float* __restrict__ a13, const float* __restrict__ a26, const float* __restrict__ a52,
    const float* __restrict__ pthresh, float* __restrict__ out,
    int total, int scan_blocks, int out_vec4)
{
    const int tid = threadIdx.x;

    // ---- tail blocks: zero-fill d_out, 4 float4 stores per thread ----
    if ((int)blockIdx.x >= scan_blocks) {
        const int zb = (blockIdx.x - scan_blocks) * 1024 + tid;
        #pragma unroll
        for (int c = 0; c < 4; c++) {
            const int zid = zb + c * 256;
            if (zid < out_vec4)
                ((float4*)out)[zid] = make_float4(0.f, 0.f, 0.f, 0.f);
        }
        return;
    }

    const int lane  = tid & 31;
    const int gbase = blockIdx.x * 1024 + tid;   // rounds at stride 256 -> coalesced
    const float thresh = __ldg(pthresh);

    // pass 1: issue 4 conf loads (MLP)
    float conf[4];
    #pragma unroll
    for (int c = 0; c < 4; c++) {
        const int gid = gbase + c * 256;
        conf[c] = -1e30f;
        if (gid < total) {
            const int n   = gid / TPI;
            const int idx = gid - n * TPI;
            if (idx < 507) {
                const int HW = 169;
                const int a = idx / HW, cell = idx - a * HW;
                conf[c] = o13[(size_t)n * 255 * HW + (a * 85) * HW + cell];
            } else if (idx < 2535) {
                const int HW = 676;
                const int p = idx - 507;
                const int a = p / HW, cell = p - a * HW;
                conf[c] = o26[(size_t)n * 255 * HW + (a * 85) * HW + cell];
            } else {
                const int HW = 2704;
                const int p = idx - 2535;
                const int a = p / HW, cell = p - a * HW;
                conf[c] = o52[(size_t)n * 255 * HW + (a * 85) * HW + cell];
            }
        }
    }

    // pass 2: per round, decode rare hits + warp-cooperative argmax
    #pragma unroll
    for (int c = 0; c < 4; c++) {
        const bool hit = conf[c] > thresh;     // gid<total implied (else -1e30)
        unsigned int mask = __ballot_sync(0xffffffffu, hit);
        if (mask == 0u) continue;

        float ox = 0.f, oy = 0.f, w = 0.f, h = 0.f;
        int   n = 0, flat = 0, sHW = 0;
        const float* cp = nullptr;

        if (hit) {
            const int gid = gbase + c * 256;
            n = gid / TPI;
            const int idx = gid - n * TPI;
            if (idx < 507) {
                const int HW = 169, H = 13;
                const int a = idx / HW, cell = idx - a * HW;
                const float* base = o13 + (size_t)n * 255 * HW;
                sHW = HW;
                const int y = cell / H, x = cell - y * H;
                const float t1 = base[(a * 85 + 1) * HW + cell];
                const float t2 = base[(a * 85 + 2) * HW + cell];
                const float t3 = base[(a * 85 + 3) * HW + cell];
                const float t4 = base[(a * 85 + 4) * HW + cell];
                ox = ((float)x + t1) * 32.f;
                oy = ((float)y + t2) * 32.f;
                w  = expf(t3) * a13[a * 2 + 0];
                h  = expf(t4) * a13[a * 2 + 1];
                cp = base + (a * 85 + 5) * HW + cell;
                flat = 0 + cell * 3 + a;
            } else if (idx < 2535) {
                const int HW = 676, H = 26;
                const int p = idx - 507;
                const int a = p / HW, cell = p - a * HW;
                const float* base = o26 + (size_t)n * 255 * HW;
                sHW = HW;
                const int y = cell / H, x = cell - y * H;
                const float t1 = base[(a * 85 + 1) * HW + cell];
                const float t2 = base[(a * 85 + 2) * HW + cell];
                const float t3 = base[(a * 85 + 3) * HW + cell];
                const float t4 = base[(a * 85 + 4) * HW + cell];
                ox = ((float)x + t1) * 16.f;
                oy = ((float)y + t2) * 16.f;
                w  = expf(t3) * a26[a * 2 + 0];
                h  = expf(t4) * a26[a * 2 + 1];
                cp = base + (a * 85 + 5) * HW + cell;
                flat = 507 + cell * 3 + a;
            } else {
                const int HW = 2704, H = 52;
                const int p = idx - 2535;
                const int a = p / HW, cell = p - a * HW;
                const float* base = o52 + (size_t)n * 255 * HW;
                sHW = HW;
                const int y = cell / H, x = cell - y * H;
                const float t1 = base[(a * 85 + 1) * HW + cell];
                const float t2 = base[(a * 85 + 2) * HW + cell];
                const float t3 = base[(a * 85 + 3) * HW + cell];
                const float t4 = base[(a * 85 + 4) * HW + cell];
                ox = ((float)x + t1) * 8.f;
                oy = ((float)y + t2) * 8.f;
                w  = expf(t3) * a52[a * 2 + 0];
                h  = expf(t4) * a52[a * 2 + 1];
                cp = base + (a * 85 + 5) * HW + cell;
                flat = 2535 + cell * 3 + a;
            }
        }

        while (mask) {
            const int src = __ffs(mask) - 1;
            mask &= mask - 1;

            const float* scp = (const float*)__shfl_sync(0xffffffffu, (unsigned long long)cp, src);
            const int    sH  = __shfl_sync(0xffffffffu, sHW, src);

            float bv = scp[(size_t)lane * sH];
            int   bk = lane;
            {
                const float v = scp[(size_t)(lane + 32) * sH];
                if (v > bv) { bv = v; bk = lane + 32; }
            }
            if (lane < 16) {
                const float v = scp[(size_t)(lane + 64) * sH];
                if (v > bv) { bv = v; bk = lane + 64; }
            }
            #pragma unroll
            for (int off = 16; off > 0; off >>= 1) {
                const float ov = __shfl_xor_sync(0xffffffffu, bv, off);
                const int   ok = __shfl_xor_sync(0xffffffffu, bk, off);
                if (ov > bv || (ov == bv && ok < bk)) { bv = ov; bk = ok; }
            }

            if (lane == src) {
                const int pos = atomicAdd(&g_cnt[n], 1);
                if (pos < MAXC) {
                    const int o = n * MAXC + pos;
                    g_conf[o] = conf[c];
                    g_ox[o]   = ox;  g_oy[o] = oy;
                    g_w[o]    = w;   g_h[o]  = h;
                    g_cls[o]  = bk;
                    g_flat[o] = flat;
                }
            }
        }
    }
}

// ============ Kernel B: PDL-overlapped rank + NMS + sparse write ============
__global__ __launch_bounds__(256) void nms_kernel(float* __restrict__ out)
{
    const int n   = blockIdx.x;
    const int tid = threadIdx.x;

    __shared__ float c_conf[MAXC];
    __shared__ int   c_flat[MAXC];
    __shared__ float r_conf[MAXC], r_ox[MAXC], r_oy[MAXC], r_w[MAXC], r_h[MAXC];
    __shared__ float r_x1[MAXC], r_y1[MAXC], r_x2[MAXC], r_y2[MAXC];
    __shared__ int   r_cls[MAXC];
    __shared__ unsigned int supw[MAXC * NW_MAX];
    __shared__ unsigned char keepf[MAXC];

    // wait for upstream scan kernel (PDL); launch overhead is already hidden
    cudaGridDependencySynchronize();

    // unconditional pool load (one entry per thread), concurrent with g_cnt load
    const int o = n * MAXC + tid;
    const float cf = g_conf[o];
    const float px = g_ox[o], py = g_oy[o], pw = g_w[o], ph = g_h[o];
    const int   pc = g_cls[o], pf = g_flat[o];
    const int   V  = min(g_cnt[n], MAXC);
    const int   K  = V;                      // V <= 256 <= K_DET

    c_conf[tid] = cf;
    c_flat[tid] = pf;
    __syncthreads();

    // rank (conf desc, tie: flat asc)
    if (tid < V) {
        int r = 0;
        for (int j = 0; j < V; j++) {
            const float cj = c_conf[j];
            if (cj > cf || (cj == cf && c_flat[j] < pf)) r++;
        }
        r_conf[r] = cf;
        r_ox[r] = px; r_oy[r] = py;
        r_w[r]  = pw; r_h[r]  = ph;
        r_cls[r] = pc;
        const float hw = pw * 0.5f, hh = ph * 0.5f;
        r_x1[r] = px - hw; r_y1[r] = py - hh;
        r_x2[r] = px + hw; r_y2[r] = py + hh;
    }
    __syncthreads();

    // suppression bit-matrix
    const int NW = (K + 31) >> 5;
    for (int t = tid; t < K * NW; t += 256) {
        const int i  = t / NW;
        const int wj = t - i * NW;
        const float x1i = r_x1[i], y1i = r_y1[i], x2i = r_x2[i], y2i = r_y2[i];
        const float areai = (x2i - x1i) * (y2i - y1i);
        const int   ci = r_cls[i];
        unsigned int word = 0;
        const int jmax = min(K, (wj + 1) * 32);
        for (int j = wj * 32; j < jmax; j++) {
            if (r_cls[j] != ci) continue;
            const float ix1 = fmaxf(x1i, r_x1[j]);
            const float iy1 = fmaxf(y1i, r_y1[j]);
            const float ix2 = fminf(x2i, r_x2[j]);
            const float iy2 = fminf(y2i, r_y2[j]);
            const float iw = fmaxf(ix2 - ix1, 0.f);
            const float ih = fmaxf(iy2 - iy1, 0.f);
            const float inter = iw * ih;
            const float areaj = (r_x2[j] - r_x1[j]) * (r_y2[j] - r_y1[j]);
            const float uni   = fmaxf(areai + areaj - inter, 1e-9f);
            if (inter / uni > 0.3f) word |= (1u << (j & 31));
        }
        supw[i * NW + wj] = word;
    }
    __syncthreads();

    // sequential greedy scan + scratch reset for graph replay
    if (tid == 0) {
        unsigned int kw[NW_MAX];
        #pragma unroll
        for (int w = 0; w < NW_MAX; w++) kw[w] = 0u;
        for (int i = 0; i < K; i++) {
            unsigned int sup = 0;
            for (int w = 0; w < NW; w++) sup |= kw[w] & supw[i * NW + w];
            if (sup == 0u) {
                kw[i >> 5] |= (1u << (i & 31));
                keepf[i] = 1;
            } else {
                keepf[i] = 0;
            }
        }
        g_cnt[n] = 0;
    }
    __syncthreads();

    // sparse write: only kept rows (rest zeroed by scan kernel)
    const float fn = (float)n;
    float* orow = out + (size_t)n * (K_DET * 7);
    for (int i = tid; i < K; i += 256) {
        if (keepf[i]) {
            float* p = orow + i * 7;
            p[0] = r_conf[i];
            p[1] = r_ox[i];
            p[2] = r_oy[i];
            p[3] = r_w[i];
            p[4] = r_h[i];
            p[5] = (float)r_cls[i];
            p[6] = fn;
        }
    }
}

extern "C" void kernel_launch(void* const* d_in, const int* in_sizes, int n_in,
                              void* d_out, int out_size) {
    const float* o13 = (const float*)d_in[0];
    const float* o26 = (const float*)d_in[1];
    const float* o52 = (const float*)d_in[2];
    const float* a13 = (const float*)d_in[3];
    const float* a26 = (const float*)d_in[4];
    const float* a52 = (const float*)d_in[5];
    const float* thr = (const float*)d_in[6];
    float* out = (float*)d_out;

    const int N = in_sizes[0] / (255 * 13 * 13);   // batch (=64)
    const int total = N * TPI;
    const int scan_blocks = (total + 1023) / 1024;     // 4 cells per thread
    const int out_vec4 = out_size / 4;
    const int zero_blocks = (out_vec4 + 1023) / 1024;  // 4 float4 per thread

    scan_kernel<<<scan_blocks + zero_blocks, 256>>>(
        o13, o26, o52, a13, a26, a52, thr, out, total, scan_blocks, out_vec4);

    // nms with programmatic dependent launch (overlap launch with scan drain)
    cudaLaunchConfig_t cfg = {};
    cfg.gridDim  = dim3((unsigned)N, 1, 1);
    cfg.blockDim = dim3(256, 1, 1);
    cfg.dynamicSmemBytes = 0;
    cfg.stream = 0;
    cudaLaunchAttribute attrs[1];
    attrs[0].id = cudaLaunchAttributeProgrammaticStreamSerialization;
    attrs[0].val.programmaticStreamSerializationAllowed = 1;
    cfg.attrs = attrs;
    cfg.numAttrs = 1;
    cudaLaunchKernelEx(&cfg, nms_kernel, out);
}